// round 5
// baseline (speedup 1.0000x reference)
#include <cuda_runtime.h>

#define HID 100
#define T   10
#define NB  5
#define G3  300
#define BT  64            // batch tile per CTA
#define BG  4             // batch groups per tile
#define RB  16            // batch elems per thread (= BT/BG)
#define NTH 400           // 100 j-lanes * BG
#define HSTR 68           // padded h row stride in floats (conflict-free)
#define B_MAX 65536

// SMEM float offsets
#define OFF_W 0           // 30000 floats : W^T [k=100][g=300]
#define OFF_H 30000       // 6800 floats  : h [k=100][HSTR]
#define OFF_A 36800       // 1024 floats  : aux (weights/biases)
#define SMEM_FLOATS 37824 // 151296 bytes

// Scratch (static device memory; kernel_launch stays allocation-free)
__device__ float g_VBUF[(T + NB) * B_MAX];   // sliding input window [slot][b]
__device__ float g_H1[T * HID * B_MAX];      // layer0 outputs [t][j][b]
__device__ float g_GI1[T * G3 * B_MAX];      // layer1 input gates [t][g][b]

__device__ __forceinline__ float sigf(float x)   { return 1.f / (1.f + __expf(-x)); }
__device__ __forceinline__ float tanhf_(float x) { return 1.f - 2.f / (__expf(2.f * x) + 1.f); }

// ---- packed fp32x2 helpers --------------------------------------------------
#define PACK2(d, s) asm("mov.b64 %0, {%1, %1};" : "=l"(d) : "f"(s))
#define FMA2(acc, a, b) asm("fma.rn.f32x2 %0, %1, %2, %0;" : "+l"(acc) : "l"(a), "l"(b))
#define UNPACK2(lo, hi, v) asm("mov.b64 {%0, %1}, %2;" : "=f"(lo), "=f"(hi) : "l"(v))

// gates[g][b] accumulation: thread (j, bg) computes r/z/n pre-activations for
// hidden unit j over its 16 batch elements (as 8 packed f32x2 accumulators each).
__device__ __forceinline__ void matvec300(const float* __restrict__ WtS,
                                          const float* __restrict__ hS,
                                          int j, int bg,
                                          unsigned long long ar[8],
                                          unsigned long long az[8],
                                          unsigned long long an[8])
{
    #pragma unroll
    for (int i = 0; i < 8; ++i) { ar[i] = 0ull; az[i] = 0ull; an[i] = 0ull; }
    const char* hbase = (const char*)(hS + bg * RB);
    #pragma unroll 2
    for (int k = 0; k < HID; ++k) {
        const float* wrow = WtS + k * G3 + j;
        float wr = wrow[0], wz = wrow[100], wn = wrow[200];
        unsigned long long wr2, wz2, wn2;
        PACK2(wr2, wr); PACK2(wz2, wz); PACK2(wn2, wn);
        const ulonglong2* hv = (const ulonglong2*)(hbase + (size_t)k * (HSTR * 4));
        #pragma unroll
        for (int u = 0; u < 4; ++u) {
            ulonglong2 h2 = hv[u];
            FMA2(ar[2*u],   h2.x, wr2);
            FMA2(ar[2*u+1], h2.y, wr2);
            FMA2(az[2*u],   h2.x, wz2);
            FMA2(az[2*u+1], h2.y, wz2);
            FMA2(an[2*u],   h2.x, wn2);
            FMA2(an[2*u+1], h2.y, wn2);
        }
    }
}

__device__ __forceinline__ void load_weightT(const float* __restrict__ W,
                                             float* __restrict__ WtS, int tid)
{
    for (int idx = tid; idx < G3 * HID; idx += NTH) {
        int row = idx / HID;
        int k   = idx - row * HID;
        WtS[k * G3 + row] = W[idx];
    }
}

__device__ __forceinline__ float gru_cell(float gi_r, float gi_z, float gi_n,
                                          float gr, float gz, float gn, float hold)
{
    float r = sigf(gi_r + gr);
    float z = sigf(gi_z + gz);
    float n = tanhf_(gi_n + r * gn);
    return (1.f - z) * n + z * hold;
}

// ---------------- init: VBUF[s][b] = x[b][s] ----------------
__global__ void k_init(const float* __restrict__ x, int B)
{
    int idx = blockIdx.x * blockDim.x + threadIdx.x;
    if (idx < B * T) {
        int b = idx / T, s = idx - b * T;
        g_VBUF[s * B + b] = x[idx];
    }
}

// ---------------- K1: layer-0 recurrence ----------------
__global__ void __launch_bounds__(NTH, 1)
k_layer0(const float* __restrict__ Whh0, const float* __restrict__ Wih0,
         const float* __restrict__ bih0, const float* __restrict__ bhh0,
         int iter, int B)
{
    extern __shared__ float sm[];
    float* WtS  = sm + OFF_W;
    float* hS   = sm + OFF_H;
    float* wihS = sm + OFF_A;
    float* bihS = sm + OFF_A + 300;
    float* bhhS = sm + OFF_A + 600;

    const int tid = threadIdx.x;
    const int j   = tid >> 2;
    const int bg  = tid & 3;
    const int bg0 = blockIdx.x * BT;

    load_weightT(Whh0, WtS, tid);
    for (int idx = tid; idx < G3; idx += NTH) {
        wihS[idx] = Wih0[idx];
        bihS[idx] = bih0[idx];
        bhhS[idx] = bhh0[idx];
    }
    for (int idx = tid; idx < HID * HSTR; idx += NTH) hS[idx] = 0.f;
    __syncthreads();

    const float wir = wihS[j], wiz = wihS[100 + j], win = wihS[200 + j];
    const float bir = bihS[j], biz = bihS[100 + j], bin = bihS[200 + j];
    const float bhr = bhhS[j], bhz = bhhS[100 + j], bhn = bhhS[200 + j];

    for (int t = 0; t < T; ++t) {
        unsigned long long ar[8], az[8], an[8];
        matvec300(WtS, hS, j, bg, ar, az, an);

        // input values for this thread's 16 batch elems
        const float4* xp = (const float4*)(g_VBUF + (size_t)(iter + t) * B + bg0 + bg * RB);
        const float4* hop = (const float4*)(hS + j * HSTR + bg * RB);
        float4 out4[4];
        #pragma unroll
        for (int u = 0; u < 4; ++u) {
            float4 xq = xp[u];
            float4 hq = hop[u];
            float a0, a1, a2, a3, z0, z1, z2, z3, n0, n1, n2, n3;
            UNPACK2(a0, a1, ar[2*u]);  UNPACK2(a2, a3, ar[2*u+1]);
            UNPACK2(z0, z1, az[2*u]);  UNPACK2(z2, z3, az[2*u+1]);
            UNPACK2(n0, n1, an[2*u]);  UNPACK2(n2, n3, an[2*u+1]);
            out4[u].x = gru_cell(xq.x*wir+bir, xq.x*wiz+biz, xq.x*win+bin, a0+bhr, z0+bhz, n0+bhn, hq.x);
            out4[u].y = gru_cell(xq.y*wir+bir, xq.y*wiz+biz, xq.y*win+bin, a1+bhr, z1+bhz, n1+bhn, hq.y);
            out4[u].z = gru_cell(xq.z*wir+bir, xq.z*wiz+biz, xq.z*win+bin, a2+bhr, z2+bhz, n2+bhn, hq.z);
            out4[u].w = gru_cell(xq.w*wir+bir, xq.w*wiz+biz, xq.w*win+bin, a3+bhr, z3+bhz, n3+bhn, hq.w);
        }
        __syncthreads();   // all reads of hS complete
        float4* hwp = (float4*)(hS + j * HSTR + bg * RB);
        float4* gwp = (float4*)(g_H1 + (size_t)(t * HID + j) * B + bg0 + bg * RB);
        #pragma unroll
        for (int u = 0; u < 4; ++u) { hwp[u] = out4[u]; gwp[u] = out4[u]; }
        __syncthreads();   // new h visible
    }
}

// ---------------- K2: GI1[t] = Wih1 * H1[t] + b_ih1 (loops all t) ----------------
__global__ void __launch_bounds__(NTH, 1)
k_gi1(const float* __restrict__ Wih1, const float* __restrict__ bih1, int B)
{
    extern __shared__ float sm[];
    float* WtS  = sm + OFF_W;
    float* hS   = sm + OFF_H;
    float* bihS = sm + OFF_A;

    const int tid = threadIdx.x;
    const int j   = tid >> 2;
    const int bg  = tid & 3;
    const int bg0 = blockIdx.x * BT;

    load_weightT(Wih1, WtS, tid);
    for (int idx = tid; idx < G3; idx += NTH) bihS[idx] = bih1[idx];
    __syncthreads();

    const float br = bihS[j], bz = bihS[100 + j], bn = bihS[200 + j];

    for (int t = 0; t < T; ++t) {
        // stage H1[t] tile into smem
        for (int idx = tid; idx < HID * BT; idx += NTH) {
            int k = idx >> 6;
            int b = idx & (BT - 1);
            hS[k * HSTR + b] = g_H1[(size_t)(t * HID + k) * B + bg0 + b];
        }
        __syncthreads();

        unsigned long long ar[8], az[8], an[8];
        matvec300(WtS, hS, j, bg, ar, az, an);

        float4* pr = (float4*)(g_GI1 + (size_t)(t * G3 +       j) * B + bg0 + bg * RB);
        float4* pz = (float4*)(g_GI1 + (size_t)(t * G3 + 100 + j) * B + bg0 + bg * RB);
        float4* pn = (float4*)(g_GI1 + (size_t)(t * G3 + 200 + j) * B + bg0 + bg * RB);
        #pragma unroll
        for (int u = 0; u < 4; ++u) {
            float a0, a1, a2, a3;
            UNPACK2(a0, a1, ar[2*u]); UNPACK2(a2, a3, ar[2*u+1]);
            pr[u] = make_float4(a0 + br, a1 + br, a2 + br, a3 + br);
            UNPACK2(a0, a1, az[2*u]); UNPACK2(a2, a3, az[2*u+1]);
            pz[u] = make_float4(a0 + bz, a1 + bz, a2 + bz, a3 + bz);
            UNPACK2(a0, a1, an[2*u]); UNPACK2(a2, a3, an[2*u+1]);
            pn[u] = make_float4(a0 + bn, a1 + bn, a2 + bn, a3 + bn);
        }
        __syncthreads();   // gemm reads done before next t overwrites hS
    }
}

// ---------------- K3: layer-1 recurrence + final linear ----------------
__global__ void __launch_bounds__(NTH, 1)
k_layer1(const float* __restrict__ Whh1, const float* __restrict__ bhh1,
         const float* __restrict__ Wlin, const float* __restrict__ blin,
         float* __restrict__ out, int iter, int B)
{
    extern __shared__ float sm[];
    float* WtS  = sm + OFF_W;
    float* hS   = sm + OFF_H;
    float* bhhS = sm + OFF_A;
    float* wlS  = sm + OFF_A + 300;

    const int tid = threadIdx.x;
    const int j   = tid >> 2;
    const int bg  = tid & 3;
    const int bg0 = blockIdx.x * BT;

    load_weightT(Whh1, WtS, tid);
    for (int idx = tid; idx < G3; idx += NTH) bhhS[idx] = bhh1[idx];
    for (int idx = tid; idx < HID; idx += NTH) wlS[idx] = Wlin[idx];
    for (int idx = tid; idx < HID * HSTR; idx += NTH) hS[idx] = 0.f;
    __syncthreads();

    const float bhr = bhhS[j], bhz = bhhS[100 + j], bhn = bhhS[200 + j];

    for (int t = 0; t < T; ++t) {
        unsigned long long ar[8], az[8], an[8];
        matvec300(WtS, hS, j, bg, ar, az, an);

        const float4* pr = (const float4*)(g_GI1 + (size_t)(t * G3 +       j) * B + bg0 + bg * RB);
        const float4* pz = (const float4*)(g_GI1 + (size_t)(t * G3 + 100 + j) * B + bg0 + bg * RB);
        const float4* pn = (const float4*)(g_GI1 + (size_t)(t * G3 + 200 + j) * B + bg0 + bg * RB);
        const float4* hop = (const float4*)(hS + j * HSTR + bg * RB);
        float4 out4[4];
        #pragma unroll
        for (int u = 0; u < 4; ++u) {
            float4 gr4 = pr[u], gz4 = pz[u], gn4 = pn[u];
            float4 hq = hop[u];
            float a0, a1, a2, a3, z0, z1, z2, z3, n0, n1, n2, n3;
            UNPACK2(a0, a1, ar[2*u]);  UNPACK2(a2, a3, ar[2*u+1]);
            UNPACK2(z0, z1, az[2*u]);  UNPACK2(z2, z3, az[2*u+1]);
            UNPACK2(n0, n1, an[2*u]);  UNPACK2(n2, n3, an[2*u+1]);
            out4[u].x = gru_cell(gr4.x, gz4.x, gn4.x, a0+bhr, z0+bhz, n0+bhn, hq.x);
            out4[u].y = gru_cell(gr4.y, gz4.y, gn4.y, a1+bhr, z1+bhz, n1+bhn, hq.y);
            out4[u].z = gru_cell(gr4.z, gz4.z, gn4.z, a2+bhr, z2+bhz, n2+bhn, hq.z);
            out4[u].w = gru_cell(gr4.w, gz4.w, gn4.w, a3+bhr, z3+bhz, n3+bhn, hq.w);
        }
        __syncthreads();
        float4* hwp = (float4*)(hS + j * HSTR + bg * RB);
        #pragma unroll
        for (int u = 0; u < 4; ++u) hwp[u] = out4[u];
        __syncthreads();
    }

    // ret = h2 @ W_lin^T + b_lin : one thread per batch element
    if (tid < BT) {
        float acc = blin[0];
        #pragma unroll 10
        for (int k = 0; k < HID; ++k) acc += hS[k * HSTR + tid] * wlS[k];
        g_VBUF[(size_t)(T + iter) * B + bg0 + tid] = acc;
        out[(bg0 + tid) * NB + iter] = acc;
    }
}

extern "C" void kernel_launch(void* const* d_in, const int* in_sizes, int n_in,
                              void* d_out, int out_size)
{
    const float* x    = (const float*)d_in[0];
    const float* Wih0 = (const float*)d_in[1];
    const float* Whh0 = (const float*)d_in[2];
    const float* bih0 = (const float*)d_in[3];
    const float* bhh0 = (const float*)d_in[4];
    const float* Wih1 = (const float*)d_in[5];
    const float* Whh1 = (const float*)d_in[6];
    const float* bih1 = (const float*)d_in[7];
    const float* bhh1 = (const float*)d_in[8];
    const float* Wlin = (const float*)d_in[9];
    const float* blin = (const float*)d_in[10];
    float* out = (float*)d_out;

    const int B = in_sizes[0] / T;              // 65536
    const int smem = SMEM_FLOATS * (int)sizeof(float);

    cudaFuncSetAttribute(k_layer0, cudaFuncAttributeMaxDynamicSharedMemorySize, smem);
    cudaFuncSetAttribute(k_gi1,    cudaFuncAttributeMaxDynamicSharedMemorySize, smem);
    cudaFuncSetAttribute(k_layer1, cudaFuncAttributeMaxDynamicSharedMemorySize, smem);

    k_init<<<(B * T + 511) / 512, 512>>>(x, B);

    const int nblk = B / BT;                    // 1024 CTAs
    for (int i = 0; i < NB; ++i) {
        k_layer0<<<nblk, NTH, smem>>>(Whh0, Wih0, bih0, bhh0, i, B);
        k_gi1  <<<nblk, NTH, smem>>>(Wih1, bih1, B);
        k_layer1<<<nblk, NTH, smem>>>(Whh1, bhh1, Wlin, blin, out, i, B);
    }
}

// round 6
// speedup vs baseline: 1.1235x; 1.1235x over previous
#include <cuda_runtime.h>

#define HID 100
#define T   10
#define NB  5
#define G3  300
#define BT  64            // batch tile per CTA
#define BG  8             // batch groups per tile
#define RB  8             // batch elems per thread (= BT/BG)
#define NTH 800           // 100 j-lanes * BG
#define HSTR 68           // padded h row stride (floats)
#define B_MAX 65536

// SMEM float offsets
#define OFF_W 0           // 40000 floats : W4 [k=100][j=100][4] = (r,z,n,pad)
#define OFF_H 40000       // 6800 floats  : h [k=100][HSTR]
#define OFF_A 46800       // 1024 floats  : aux
#define SMEM_FLOATS 47824 // 191296 bytes

// Scratch (static device memory; kernel_launch stays allocation-free)
__device__ float g_VBUF[(T + NB) * B_MAX];   // sliding input window [slot][b]
__device__ float g_H1[T * HID * B_MAX];      // layer0 outputs [t][j][b]
__device__ float g_GI1[T * G3 * B_MAX];      // layer1 input gates [t][g][b]

__device__ __forceinline__ float sigf(float x)   { return 1.f / (1.f + __expf(-x)); }
__device__ __forceinline__ float tanhf_(float x) { return 1.f - 2.f / (__expf(2.f * x) + 1.f); }

// ---- packed fp32x2 helpers ----
#define PACK2(d, s) asm("mov.b64 %0, {%1, %1};" : "=l"(d) : "f"(s))
#define FMA2(acc, a, b) asm("fma.rn.f32x2 %0, %1, %2, %0;" : "+l"(acc) : "l"(a), "l"(b))
#define UNPACK2(lo, hi, v) asm("mov.b64 {%0, %1}, %2;" : "=f"(lo), "=f"(hi) : "l"(v))

// Thread (j, bg) accumulates r/z/n pre-activations for hidden unit j over its
// 8 batch elements (4 packed f32x2 accumulators per gate).
// Per k: 1 LDS.128 (W4, conflict-free) + 2 LDS.128 (h, broadcast) + 12 FFMA2.
__device__ __forceinline__ void matvec300(const float* __restrict__ WtS,
                                          const float* __restrict__ hS,
                                          int j, int bg,
                                          unsigned long long ar[4],
                                          unsigned long long az[4],
                                          unsigned long long an[4])
{
    #pragma unroll
    for (int i = 0; i < 4; ++i) { ar[i] = 0ull; az[i] = 0ull; an[i] = 0ull; }
    const float4* __restrict__ wp = (const float4*)WtS + j;
    const char*   __restrict__ hb = (const char*)(hS + bg * RB);
    #pragma unroll 2
    for (int k = 0; k < HID; ++k) {
        float4 w4 = wp[k * HID];
        unsigned long long wr2, wz2, wn2;
        PACK2(wr2, w4.x); PACK2(wz2, w4.y); PACK2(wn2, w4.z);
        const ulonglong2* hv = (const ulonglong2*)(hb + (size_t)k * (HSTR * 4));
        ulonglong2 h0 = hv[0];
        ulonglong2 h1 = hv[1];
        FMA2(ar[0], h0.x, wr2);  FMA2(ar[1], h0.y, wr2);
        FMA2(ar[2], h1.x, wr2);  FMA2(ar[3], h1.y, wr2);
        FMA2(az[0], h0.x, wz2);  FMA2(az[1], h0.y, wz2);
        FMA2(az[2], h1.x, wz2);  FMA2(az[3], h1.y, wz2);
        FMA2(an[0], h0.x, wn2);  FMA2(an[1], h0.y, wn2);
        FMA2(an[2], h1.x, wn2);  FMA2(an[3], h1.y, wn2);
    }
}

// W (global, [g=300][k=100]) -> smem [k][j][4] with gate = g/100, j = g%100
__device__ __forceinline__ void load_weightT4(const float* __restrict__ W,
                                              float* __restrict__ WtS, int tid)
{
    for (int idx = tid; idx < G3 * HID; idx += NTH) {
        int g = idx / HID;
        int k = idx - g * HID;
        int gate = g / HID;          // 0,1,2
        int j    = g - gate * HID;
        WtS[(k * HID + j) * 4 + gate] = W[idx];
    }
}

__device__ __forceinline__ float gru_cell(float gi_r, float gi_z, float gi_n,
                                          float gr, float gz, float gn, float hold)
{
    float r = sigf(gi_r + gr);
    float z = sigf(gi_z + gz);
    float n = tanhf_(gi_n + r * gn);
    return (1.f - z) * n + z * hold;
}

// ---------------- init: VBUF[s][b] = x[b][s] ----------------
__global__ void k_init(const float* __restrict__ x, int B)
{
    int idx = blockIdx.x * blockDim.x + threadIdx.x;
    if (idx < B * T) {
        int b = idx / T, s = idx - b * T;
        g_VBUF[s * B + b] = x[idx];
    }
}

// ---------------- K1: layer-0 recurrence ----------------
__global__ void __launch_bounds__(NTH, 1)
k_layer0(const float* __restrict__ Whh0, const float* __restrict__ Wih0,
         const float* __restrict__ bih0, const float* __restrict__ bhh0,
         int iter, int B)
{
    extern __shared__ float sm[];
    float* WtS  = sm + OFF_W;
    float* hS   = sm + OFF_H;
    float* wihS = sm + OFF_A;
    float* bihS = sm + OFF_A + 304;
    float* bhhS = sm + OFF_A + 608;

    const int tid = threadIdx.x;
    const int j   = tid >> 3;
    const int bg  = tid & 7;
    const int bg0 = blockIdx.x * BT;

    load_weightT4(Whh0, WtS, tid);
    for (int idx = tid; idx < G3; idx += NTH) {
        wihS[idx] = Wih0[idx];
        bihS[idx] = bih0[idx];
        bhhS[idx] = bhh0[idx];
    }
    for (int idx = tid; idx < HID * HSTR; idx += NTH) hS[idx] = 0.f;
    __syncthreads();

    const float wir = wihS[j], wiz = wihS[100 + j], win = wihS[200 + j];
    const float bir = bihS[j], biz = bihS[100 + j], bin = bihS[200 + j];
    const float bhr = bhhS[j], bhz = bhhS[100 + j], bhn = bhhS[200 + j];

    for (int t = 0; t < T; ++t) {
        unsigned long long ar[4], az[4], an[4];
        matvec300(WtS, hS, j, bg, ar, az, an);

        const float4* xp  = (const float4*)(g_VBUF + (size_t)(iter + t) * B + bg0 + bg * RB);
        const float4* hop = (const float4*)(hS + j * HSTR + bg * RB);
        float4 out4[2];
        #pragma unroll
        for (int u = 0; u < 2; ++u) {
            float4 xq = xp[u];
            float4 hq = hop[u];
            float a0, a1, a2, a3, z0, z1, z2, z3, n0, n1, n2, n3;
            UNPACK2(a0, a1, ar[2*u]);  UNPACK2(a2, a3, ar[2*u+1]);
            UNPACK2(z0, z1, az[2*u]);  UNPACK2(z2, z3, az[2*u+1]);
            UNPACK2(n0, n1, an[2*u]);  UNPACK2(n2, n3, an[2*u+1]);
            out4[u].x = gru_cell(xq.x*wir+bir, xq.x*wiz+biz, xq.x*win+bin, a0+bhr, z0+bhz, n0+bhn, hq.x);
            out4[u].y = gru_cell(xq.y*wir+bir, xq.y*wiz+biz, xq.y*win+bin, a1+bhr, z1+bhz, n1+bhn, hq.y);
            out4[u].z = gru_cell(xq.z*wir+bir, xq.z*wiz+biz, xq.z*win+bin, a2+bhr, z2+bhz, n2+bhn, hq.z);
            out4[u].w = gru_cell(xq.w*wir+bir, xq.w*wiz+biz, xq.w*win+bin, a3+bhr, z3+bhz, n3+bhn, hq.w);
        }
        __syncthreads();
        float4* hwp = (float4*)(hS + j * HSTR + bg * RB);
        float4* gwp = (float4*)(g_H1 + (size_t)(t * HID + j) * B + bg0 + bg * RB);
        hwp[0] = out4[0]; hwp[1] = out4[1];
        gwp[0] = out4[0]; gwp[1] = out4[1];
        __syncthreads();
    }
}

// ---------------- K2: GI1[t] = Wih1 * H1[t] + b_ih1 (loops all t) ----------------
__global__ void __launch_bounds__(NTH, 1)
k_gi1(const float* __restrict__ Wih1, const float* __restrict__ bih1, int B)
{
    extern __shared__ float sm[];
    float* WtS  = sm + OFF_W;
    float* hS   = sm + OFF_H;
    float* bihS = sm + OFF_A;

    const int tid = threadIdx.x;
    const int j   = tid >> 3;
    const int bg  = tid & 7;
    const int bg0 = blockIdx.x * BT;

    load_weightT4(Wih1, WtS, tid);
    for (int idx = tid; idx < G3; idx += NTH) bihS[idx] = bih1[idx];
    __syncthreads();

    const float br = bihS[j], bz = bihS[100 + j], bn = bihS[200 + j];

    for (int t = 0; t < T; ++t) {
        for (int idx = tid; idx < HID * BT; idx += NTH) {
            int k = idx >> 6;
            int b = idx & (BT - 1);
            hS[k * HSTR + b] = g_H1[(size_t)(t * HID + k) * B + bg0 + b];
        }
        __syncthreads();

        unsigned long long ar[4], az[4], an[4];
        matvec300(WtS, hS, j, bg, ar, az, an);

        float4* pr = (float4*)(g_GI1 + (size_t)(t * G3 +       j) * B + bg0 + bg * RB);
        float4* pz = (float4*)(g_GI1 + (size_t)(t * G3 + 100 + j) * B + bg0 + bg * RB);
        float4* pn = (float4*)(g_GI1 + (size_t)(t * G3 + 200 + j) * B + bg0 + bg * RB);
        #pragma unroll
        for (int u = 0; u < 2; ++u) {
            float a0, a1, a2, a3;
            UNPACK2(a0, a1, ar[2*u]); UNPACK2(a2, a3, ar[2*u+1]);
            pr[u] = make_float4(a0 + br, a1 + br, a2 + br, a3 + br);
            UNPACK2(a0, a1, az[2*u]); UNPACK2(a2, a3, az[2*u+1]);
            pz[u] = make_float4(a0 + bz, a1 + bz, a2 + bz, a3 + bz);
            UNPACK2(a0, a1, an[2*u]); UNPACK2(a2, a3, an[2*u+1]);
            pn[u] = make_float4(a0 + bn, a1 + bn, a2 + bn, a3 + bn);
        }
        __syncthreads();
    }
}

// ---------------- K3: layer-1 recurrence + final linear ----------------
__global__ void __launch_bounds__(NTH, 1)
k_layer1(const float* __restrict__ Whh1, const float* __restrict__ bhh1,
         const float* __restrict__ Wlin, const float* __restrict__ blin,
         float* __restrict__ out, int iter, int B)
{
    extern __shared__ float sm[];
    float* WtS  = sm + OFF_W;
    float* hS   = sm + OFF_H;
    float* bhhS = sm + OFF_A;
    float* wlS  = sm + OFF_A + 304;

    const int tid = threadIdx.x;
    const int j   = tid >> 3;
    const int bg  = tid & 7;
    const int bg0 = blockIdx.x * BT;

    load_weightT4(Whh1, WtS, tid);
    for (int idx = tid; idx < G3; idx += NTH) bhhS[idx] = bhh1[idx];
    for (int idx = tid; idx < HID; idx += NTH) wlS[idx] = Wlin[idx];
    for (int idx = tid; idx < HID * HSTR; idx += NTH) hS[idx] = 0.f;
    __syncthreads();

    const float bhr = bhhS[j], bhz = bhhS[100 + j], bhn = bhhS[200 + j];

    for (int t = 0; t < T; ++t) {
        unsigned long long ar[4], az[4], an[4];
        matvec300(WtS, hS, j, bg, ar, az, an);

        const float4* pr = (const float4*)(g_GI1 + (size_t)(t * G3 +       j) * B + bg0 + bg * RB);
        const float4* pz = (const float4*)(g_GI1 + (size_t)(t * G3 + 100 + j) * B + bg0 + bg * RB);
        const float4* pn = (const float4*)(g_GI1 + (size_t)(t * G3 + 200 + j) * B + bg0 + bg * RB);
        const float4* hop = (const float4*)(hS + j * HSTR + bg * RB);
        float4 out4[2];
        #pragma unroll
        for (int u = 0; u < 2; ++u) {
            float4 gr4 = pr[u], gz4 = pz[u], gn4 = pn[u];
            float4 hq = hop[u];
            float a0, a1, a2, a3, z0, z1, z2, z3, n0, n1, n2, n3;
            UNPACK2(a0, a1, ar[2*u]);  UNPACK2(a2, a3, ar[2*u+1]);
            UNPACK2(z0, z1, az[2*u]);  UNPACK2(z2, z3, az[2*u+1]);
            UNPACK2(n0, n1, an[2*u]);  UNPACK2(n2, n3, an[2*u+1]);
            out4[u].x = gru_cell(gr4.x, gz4.x, gn4.x, a0+bhr, z0+bhz, n0+bhn, hq.x);
            out4[u].y = gru_cell(gr4.y, gz4.y, gn4.y, a1+bhr, z1+bhz, n1+bhn, hq.y);
            out4[u].z = gru_cell(gr4.z, gz4.z, gn4.z, a2+bhr, z2+bhz, n2+bhn, hq.z);
            out4[u].w = gru_cell(gr4.w, gz4.w, gn4.w, a3+bhr, z3+bhz, n3+bhn, hq.w);
        }
        __syncthreads();
        float4* hwp = (float4*)(hS + j * HSTR + bg * RB);
        hwp[0] = out4[0]; hwp[1] = out4[1];
        __syncthreads();
    }

    // ret = h2 @ W_lin^T + b_lin : one thread per batch element
    if (tid < BT) {
        float acc = blin[0];
        #pragma unroll 10
        for (int k = 0; k < HID; ++k) acc += hS[k * HSTR + tid] * wlS[k];
        g_VBUF[(size_t)(T + iter) * B + bg0 + tid] = acc;
        out[(bg0 + tid) * NB + iter] = acc;
    }
}

extern "C" void kernel_launch(void* const* d_in, const int* in_sizes, int n_in,
                              void* d_out, int out_size)
{
    const float* x    = (const float*)d_in[0];
    const float* Wih0 = (const float*)d_in[1];
    const float* Whh0 = (const float*)d_in[2];
    const float* bih0 = (const float*)d_in[3];
    const float* bhh0 = (const float*)d_in[4];
    const float* Wih1 = (const float*)d_in[5];
    const float* Whh1 = (const float*)d_in[6];
    const float* bih1 = (const float*)d_in[7];
    const float* bhh1 = (const float*)d_in[8];
    const float* Wlin = (const float*)d_in[9];
    const float* blin = (const float*)d_in[10];
    float* out = (float*)d_out;

    const int B = in_sizes[0] / T;              // 65536
    const int smem = SMEM_FLOATS * (int)sizeof(float);

    cudaFuncSetAttribute(k_layer0, cudaFuncAttributeMaxDynamicSharedMemorySize, smem);
    cudaFuncSetAttribute(k_gi1,    cudaFuncAttributeMaxDynamicSharedMemorySize, smem);
    cudaFuncSetAttribute(k_layer1, cudaFuncAttributeMaxDynamicSharedMemorySize, smem);

    k_init<<<(B * T + 511) / 512, 512>>>(x, B);

    const int nblk = B / BT;                    // 1024 CTAs, ~6.92 waves
    for (int i = 0; i < NB; ++i) {
        k_layer0<<<nblk, NTH, smem>>>(Whh0, Wih0, bih0, bhh0, i, B);
        k_gi1  <<<nblk, NTH, smem>>>(Wih1, bih1, B);
        k_layer1<<<nblk, NTH, smem>>>(Whh1, bhh1, Wlin, blin, out, i, B);
    }
}

// round 7
// speedup vs baseline: 1.7513x; 1.5588x over previous
#include <cuda_runtime.h>

#define HID 100
#define T   10
#define NB  5
#define G3  300
#define BT  64            // batch tile per CTA
#define JP  50            // j-pairs
#define NTH 400           // 50 jp-lanes * 8 batch-groups
#define B_MAX 65536

// SMEM float offsets
#define OFF_W 0           // 30000 floats : W6 [k=100][jp=50][6] = r0,z0,n0,r1,z1,n1
#define OFF_H 30000       // 6400 floats  : h [k=100][64]
#define OFF_A 36400       // 1024 floats  : aux
#define SMEM_FLOATS 37424 // 149696 bytes

// Scratch (static device memory; kernel_launch stays allocation-free)
__device__ float g_VBUF[(T + NB) * B_MAX];   // sliding input window [slot][b]
__device__ float g_H1[T * HID * B_MAX];      // layer0 outputs [t][j][b]
__device__ float g_GI1[T * G3 * B_MAX];      // layer1 input gates [t][g][b]

__device__ __forceinline__ float sigf(float x)   { return 1.f / (1.f + __expf(-x)); }
__device__ __forceinline__ float tanhf_(float x) { return 1.f - 2.f / (__expf(2.f * x) + 1.f); }

// ---- packed fp32x2 helpers ----
#define PACK2(d, s) asm("mov.b64 %0, {%1, %1};" : "=l"(d) : "f"(s))
#define FMA2(acc, a, b) asm("fma.rn.f32x2 %0, %1, %2, %0;" : "+l"(acc) : "l"(a), "l"(b))
#define UNPACK2(lo, hi, v) asm("mov.b64 {%0, %1}, %2;" : "=f"(lo), "=f"(hi) : "l"(v))

// Accumulator index: [j(2)][gate(3)][q(4)] ; q: 0={4bg,4bg+1} 1={4bg+2,4bg+3}
//                                            2={32+4bg,+1}  3={32+4bg+2,+3}
#define AIX(j, g, q) ((j) * 12 + (g) * 4 + (q))

// Per thread-k: 3 LDS.64 (w6) + 2 LDS.128 (h) + 6 PACK2 + 24 FFMA2 = 48 MACs
__device__ __forceinline__ void matvec_jp(const float* __restrict__ WtS,
                                          const float* __restrict__ hS,
                                          int jp, int bg,
                                          unsigned long long acc[24])
{
    #pragma unroll
    for (int i = 0; i < 24; ++i) acc[i] = 0ull;
    const float2* __restrict__ wb = (const float2*)(WtS + jp * 6);
    const float*  __restrict__ hb = hS + 4 * bg;
    #pragma unroll 5
    for (int k = 0; k < HID; ++k) {
        float2 w01 = wb[k * 150 + 0];   // r0, z0
        float2 w23 = wb[k * 150 + 1];   // n0, r1
        float2 w45 = wb[k * 150 + 2];   // z1, n1
        unsigned long long wr0, wz0, wn0, wr1, wz1, wn1;
        PACK2(wr0, w01.x); PACK2(wz0, w01.y); PACK2(wn0, w23.x);
        PACK2(wr1, w23.y); PACK2(wz1, w45.x); PACK2(wn1, w45.y);
        ulonglong2 hl = *(const ulonglong2*)(hb + k * 64);        // b: 4bg..4bg+3
        ulonglong2 hh = *(const ulonglong2*)(hb + k * 64 + 32);   // b: 32+4bg..+3
        FMA2(acc[AIX(0,0,0)], hl.x, wr0); FMA2(acc[AIX(0,0,1)], hl.y, wr0);
        FMA2(acc[AIX(0,0,2)], hh.x, wr0); FMA2(acc[AIX(0,0,3)], hh.y, wr0);
        FMA2(acc[AIX(0,1,0)], hl.x, wz0); FMA2(acc[AIX(0,1,1)], hl.y, wz0);
        FMA2(acc[AIX(0,1,2)], hh.x, wz0); FMA2(acc[AIX(0,1,3)], hh.y, wz0);
        FMA2(acc[AIX(0,2,0)], hl.x, wn0); FMA2(acc[AIX(0,2,1)], hl.y, wn0);
        FMA2(acc[AIX(0,2,2)], hh.x, wn0); FMA2(acc[AIX(0,2,3)], hh.y, wn0);
        FMA2(acc[AIX(1,0,0)], hl.x, wr1); FMA2(acc[AIX(1,0,1)], hl.y, wr1);
        FMA2(acc[AIX(1,0,2)], hh.x, wr1); FMA2(acc[AIX(1,0,3)], hh.y, wr1);
        FMA2(acc[AIX(1,1,0)], hl.x, wz1); FMA2(acc[AIX(1,1,1)], hl.y, wz1);
        FMA2(acc[AIX(1,1,2)], hh.x, wz1); FMA2(acc[AIX(1,1,3)], hh.y, wz1);
        FMA2(acc[AIX(1,2,0)], hl.x, wn1); FMA2(acc[AIX(1,2,1)], hl.y, wn1);
        FMA2(acc[AIX(1,2,2)], hh.x, wn1); FMA2(acc[AIX(1,2,3)], hh.y, wn1);
    }
}

// Global W [g=300][k=100] -> smem W6 [k][jp][6], slot = (j&1)*3 + gate
__device__ __forceinline__ void load_weight6(const float* __restrict__ W,
                                             float* __restrict__ WtS, int tid)
{
    for (int idx = tid; idx < G3 * HID; idx += NTH) {
        int g = idx / HID;
        int k = idx - g * HID;
        int gate = g / HID;
        int j    = g - gate * HID;
        WtS[k * G3 + (j >> 1) * 6 + (j & 1) * 3 + gate] = W[idx];
    }
}

__device__ __forceinline__ float gru_cell(float gi_r, float gi_z, float gi_n,
                                          float gr, float gz, float gn, float hold)
{
    float r = sigf(gi_r + gr);
    float z = sigf(gi_z + gz);
    float n = tanhf_(gi_n + r * gn);
    return (1.f - z) * n + z * hold;
}

// unpack one j's 12 accumulators into 8 floats per gate
#define UNPACK_J(jj, R, Z, N, acc) \
    UNPACK2(R[0], R[1], acc[AIX(jj,0,0)]); UNPACK2(R[2], R[3], acc[AIX(jj,0,1)]); \
    UNPACK2(R[4], R[5], acc[AIX(jj,0,2)]); UNPACK2(R[6], R[7], acc[AIX(jj,0,3)]); \
    UNPACK2(Z[0], Z[1], acc[AIX(jj,1,0)]); UNPACK2(Z[2], Z[3], acc[AIX(jj,1,1)]); \
    UNPACK2(Z[4], Z[5], acc[AIX(jj,1,2)]); UNPACK2(Z[6], Z[7], acc[AIX(jj,1,3)]); \
    UNPACK2(N[0], N[1], acc[AIX(jj,2,0)]); UNPACK2(N[2], N[3], acc[AIX(jj,2,1)]); \
    UNPACK2(N[4], N[5], acc[AIX(jj,2,2)]); UNPACK2(N[6], N[7], acc[AIX(jj,2,3)])

// ---------------- init: VBUF[s][b] = x[b][s] ----------------
__global__ void k_init(const float* __restrict__ x, int B)
{
    int idx = blockIdx.x * blockDim.x + threadIdx.x;
    if (idx < B * T) {
        int b = idx / T, s = idx - b * T;
        g_VBUF[s * B + b] = x[idx];
    }
}

// ---------------- K1: layer-0 recurrence ----------------
__global__ void __launch_bounds__(NTH, 1)
k_layer0(const float* __restrict__ Whh0, const float* __restrict__ Wih0,
         const float* __restrict__ bih0, const float* __restrict__ bhh0,
         int iter, int B)
{
    extern __shared__ float sm[];
    float* WtS = sm + OFF_W;
    float* hS  = sm + OFF_H;
    float* auxS = sm + OFF_A;   // [0:300) wih, [304:604) bih, [608:908) bhh

    const int tid = threadIdx.x;
    const int jp  = tid >> 3;
    const int bg  = tid & 7;
    const int bg0 = blockIdx.x * BT;
    const int j0  = 2 * jp, j1 = 2 * jp + 1;

    load_weight6(Whh0, WtS, tid);
    for (int idx = tid; idx < G3; idx += NTH) {
        auxS[idx]       = Wih0[idx];
        auxS[304 + idx] = bih0[idx];
        auxS[608 + idx] = bhh0[idx];
    }
    for (int idx = tid; idx < HID * BT; idx += NTH) hS[idx] = 0.f;
    __syncthreads();

    const float wir0 = auxS[j0],       wiz0 = auxS[100 + j0], win0 = auxS[200 + j0];
    const float wir1 = auxS[j1],       wiz1 = auxS[100 + j1], win1 = auxS[200 + j1];
    const float bir0 = auxS[304 + j0], biz0 = auxS[404 + j0], bin0 = auxS[504 + j0];
    const float bir1 = auxS[304 + j1], biz1 = auxS[404 + j1], bin1 = auxS[504 + j1];
    const float bhr0 = auxS[608 + j0], bhz0 = auxS[708 + j0], bhn0 = auxS[808 + j0];
    const float bhr1 = auxS[608 + j1], bhz1 = auxS[708 + j1], bhn1 = auxS[808 + j1];

    for (int t = 0; t < T; ++t) {
        unsigned long long acc[24];
        matvec_jp(WtS, hS, jp, bg, acc);

        // x for this thread's 8 batches (L1/L2 cached across jp groups)
        const float* xb = g_VBUF + (size_t)(iter + t) * B + bg0 + 4 * bg;
        float4 xlo = *(const float4*)xb;
        float4 xhi = *(const float4*)(xb + 32);
        float xv[8] = {xlo.x, xlo.y, xlo.z, xlo.w, xhi.x, xhi.y, xhi.z, xhi.w};

        float h0o[8], h1o[8];
        *(float4*)(h0o)     = *(const float4*)(hS + j0 * 64 + 4 * bg);
        *(float4*)(h0o + 4) = *(const float4*)(hS + j0 * 64 + 32 + 4 * bg);
        *(float4*)(h1o)     = *(const float4*)(hS + j1 * 64 + 4 * bg);
        *(float4*)(h1o + 4) = *(const float4*)(hS + j1 * 64 + 32 + 4 * bg);

        float R[8], Z[8], N[8], hn0[8], hn1[8];
        UNPACK_J(0, R, Z, N, acc);
        #pragma unroll
        for (int i = 0; i < 8; ++i)
            hn0[i] = gru_cell(xv[i]*wir0 + bir0, xv[i]*wiz0 + biz0, xv[i]*win0 + bin0,
                              R[i] + bhr0, Z[i] + bhz0, N[i] + bhn0, h0o[i]);
        UNPACK_J(1, R, Z, N, acc);
        #pragma unroll
        for (int i = 0; i < 8; ++i)
            hn1[i] = gru_cell(xv[i]*wir1 + bir1, xv[i]*wiz1 + biz1, xv[i]*win1 + bin1,
                              R[i] + bhr1, Z[i] + bhz1, N[i] + bhn1, h1o[i]);

        __syncthreads();   // all matvec/h_old reads of hS complete
        *(float4*)(hS + j0 * 64 + 4 * bg)      = *(float4*)(hn0);
        *(float4*)(hS + j0 * 64 + 32 + 4 * bg) = *(float4*)(hn0 + 4);
        *(float4*)(hS + j1 * 64 + 4 * bg)      = *(float4*)(hn1);
        *(float4*)(hS + j1 * 64 + 32 + 4 * bg) = *(float4*)(hn1 + 4);
        float* gw0 = g_H1 + (size_t)(t * HID + j0) * B + bg0 + 4 * bg;
        float* gw1 = g_H1 + (size_t)(t * HID + j1) * B + bg0 + 4 * bg;
        *(float4*)(gw0)      = *(float4*)(hn0);
        *(float4*)(gw0 + 32) = *(float4*)(hn0 + 4);
        *(float4*)(gw1)      = *(float4*)(hn1);
        *(float4*)(gw1 + 32) = *(float4*)(hn1 + 4);
        __syncthreads();
    }
}

// ---------------- K2: GI1[t] = Wih1 * H1[t] + b_ih1 (loops all t) ----------------
__global__ void __launch_bounds__(NTH, 1)
k_gi1(const float* __restrict__ Wih1, const float* __restrict__ bih1, int B)
{
    extern __shared__ float sm[];
    float* WtS  = sm + OFF_W;
    float* hS   = sm + OFF_H;
    float* auxS = sm + OFF_A;

    const int tid = threadIdx.x;
    const int jp  = tid >> 3;
    const int bg  = tid & 7;
    const int bg0 = blockIdx.x * BT;
    const int j0  = 2 * jp, j1 = 2 * jp + 1;

    load_weight6(Wih1, WtS, tid);
    for (int idx = tid; idx < G3; idx += NTH) auxS[idx] = bih1[idx];
    __syncthreads();

    const float br0 = auxS[j0], bz0 = auxS[100 + j0], bn0 = auxS[200 + j0];
    const float br1 = auxS[j1], bz1 = auxS[100 + j1], bn1 = auxS[200 + j1];

    for (int t = 0; t < T; ++t) {
        // stage H1[t] (coalesced: 16 threads cover one 64-float k-row)
        for (int idx = tid * 4; idx < HID * BT; idx += NTH * 4)
            *(float4*)(hS + idx) = *(const float4*)(g_H1 + (size_t)t * HID * B
                                      + (size_t)(idx >> 6) * B + bg0 + (idx & 63));
        __syncthreads();

        unsigned long long acc[24];
        matvec_jp(WtS, hS, jp, bg, acc);

        float R[8], Z[8], N[8];
        float* gbase = g_GI1 + (size_t)t * G3 * B + bg0 + 4 * bg;
        UNPACK_J(0, R, Z, N, acc);
        { float* p = gbase + (size_t)j0 * B;
          *(float4*)(p)      = make_float4(R[0]+br0, R[1]+br0, R[2]+br0, R[3]+br0);
          *(float4*)(p + 32) = make_float4(R[4]+br0, R[5]+br0, R[6]+br0, R[7]+br0);
          p = gbase + (size_t)(100 + j0) * B;
          *(float4*)(p)      = make_float4(Z[0]+bz0, Z[1]+bz0, Z[2]+bz0, Z[3]+bz0);
          *(float4*)(p + 32) = make_float4(Z[4]+bz0, Z[5]+bz0, Z[6]+bz0, Z[7]+bz0);
          p = gbase + (size_t)(200 + j0) * B;
          *(float4*)(p)      = make_float4(N[0]+bn0, N[1]+bn0, N[2]+bn0, N[3]+bn0);
          *(float4*)(p + 32) = make_float4(N[4]+bn0, N[5]+bn0, N[6]+bn0, N[7]+bn0); }
        UNPACK_J(1, R, Z, N, acc);
        { float* p = gbase + (size_t)j1 * B;
          *(float4*)(p)      = make_float4(R[0]+br1, R[1]+br1, R[2]+br1, R[3]+br1);
          *(float4*)(p + 32) = make_float4(R[4]+br1, R[5]+br1, R[6]+br1, R[7]+br1);
          p = gbase + (size_t)(100 + j1) * B;
          *(float4*)(p)      = make_float4(Z[0]+bz1, Z[1]+bz1, Z[2]+bz1, Z[3]+bz1);
          *(float4*)(p + 32) = make_float4(Z[4]+bz1, Z[5]+bz1, Z[6]+bz1, Z[7]+bz1);
          p = gbase + (size_t)(200 + j1) * B;
          *(float4*)(p)      = make_float4(N[0]+bn1, N[1]+bn1, N[2]+bn1, N[3]+bn1);
          *(float4*)(p + 32) = make_float4(N[4]+bn1, N[5]+bn1, N[6]+bn1, N[7]+bn1); }
        __syncthreads();
    }
}

// ---------------- K3: layer-1 recurrence + final linear ----------------
__global__ void __launch_bounds__(NTH, 1)
k_layer1(const float* __restrict__ Whh1, const float* __restrict__ bhh1,
         const float* __restrict__ Wlin, const float* __restrict__ blin,
         float* __restrict__ out, int iter, int B)
{
    extern __shared__ float sm[];
    float* WtS  = sm + OFF_W;
    float* hS   = sm + OFF_H;
    float* auxS = sm + OFF_A;   // [0:300) bhh, [304:404) wlin

    const int tid = threadIdx.x;
    const int jp  = tid >> 3;
    const int bg  = tid & 7;
    const int bg0 = blockIdx.x * BT;
    const int j0  = 2 * jp, j1 = 2 * jp + 1;

    load_weight6(Whh1, WtS, tid);
    for (int idx = tid; idx < G3; idx += NTH) auxS[idx] = bhh1[idx];
    for (int idx = tid; idx < HID; idx += NTH) auxS[304 + idx] = Wlin[idx];
    for (int idx = tid; idx < HID * BT; idx += NTH) hS[idx] = 0.f;
    __syncthreads();

    const float bhr0 = auxS[j0], bhz0 = auxS[100 + j0], bhn0 = auxS[200 + j0];
    const float bhr1 = auxS[j1], bhz1 = auxS[100 + j1], bhn1 = auxS[200 + j1];

    for (int t = 0; t < T; ++t) {
        unsigned long long acc[24];
        matvec_jp(WtS, hS, jp, bg, acc);

        const float* gbase = g_GI1 + (size_t)t * G3 * B + bg0 + 4 * bg;
        float gir0[8], giz0[8], gin0[8], gir1[8], giz1[8], gin1[8];
        *(float4*)(gir0)     = *(const float4*)(gbase + (size_t)j0 * B);
        *(float4*)(gir0 + 4) = *(const float4*)(gbase + (size_t)j0 * B + 32);
        *(float4*)(giz0)     = *(const float4*)(gbase + (size_t)(100 + j0) * B);
        *(float4*)(giz0 + 4) = *(const float4*)(gbase + (size_t)(100 + j0) * B + 32);
        *(float4*)(gin0)     = *(const float4*)(gbase + (size_t)(200 + j0) * B);
        *(float4*)(gin0 + 4) = *(const float4*)(gbase + (size_t)(200 + j0) * B + 32);
        *(float4*)(gir1)     = *(const float4*)(gbase + (size_t)j1 * B);
        *(float4*)(gir1 + 4) = *(const float4*)(gbase + (size_t)j1 * B + 32);
        *(float4*)(giz1)     = *(const float4*)(gbase + (size_t)(100 + j1) * B);
        *(float4*)(giz1 + 4) = *(const float4*)(gbase + (size_t)(100 + j1) * B + 32);
        *(float4*)(gin1)     = *(const float4*)(gbase + (size_t)(200 + j1) * B);
        *(float4*)(gin1 + 4) = *(const float4*)(gbase + (size_t)(200 + j1) * B + 32);

        float h0o[8], h1o[8];
        *(float4*)(h0o)     = *(const float4*)(hS + j0 * 64 + 4 * bg);
        *(float4*)(h0o + 4) = *(const float4*)(hS + j0 * 64 + 32 + 4 * bg);
        *(float4*)(h1o)     = *(const float4*)(hS + j1 * 64 + 4 * bg);
        *(float4*)(h1o + 4) = *(const float4*)(hS + j1 * 64 + 32 + 4 * bg);

        float R[8], Z[8], N[8], hn0[8], hn1[8];
        UNPACK_J(0, R, Z, N, acc);
        #pragma unroll
        for (int i = 0; i < 8; ++i)
            hn0[i] = gru_cell(gir0[i], giz0[i], gin0[i],
                              R[i] + bhr0, Z[i] + bhz0, N[i] + bhn0, h0o[i]);
        UNPACK_J(1, R, Z, N, acc);
        #pragma unroll
        for (int i = 0; i < 8; ++i)
            hn1[i] = gru_cell(gir1[i], giz1[i], gin1[i],
                              R[i] + bhr1, Z[i] + bhz1, N[i] + bhn1, h1o[i]);

        __syncthreads();
        *(float4*)(hS + j0 * 64 + 4 * bg)      = *(float4*)(hn0);
        *(float4*)(hS + j0 * 64 + 32 + 4 * bg) = *(float4*)(hn0 + 4);
        *(float4*)(hS + j1 * 64 + 4 * bg)      = *(float4*)(hn1);
        *(float4*)(hS + j1 * 64 + 32 + 4 * bg) = *(float4*)(hn1 + 4);
        __syncthreads();
    }

    // ret = h2 @ W_lin^T + b_lin : one thread per batch element
    if (tid < BT) {
        float acc = blin[0];
        #pragma unroll 10
        for (int k = 0; k < HID; ++k) acc += hS[k * 64 + tid] * auxS[304 + k];
        g_VBUF[(size_t)(T + iter) * B + bg0 + tid] = acc;
        out[(bg0 + tid) * NB + iter] = acc;
    }
}

extern "C" void kernel_launch(void* const* d_in, const int* in_sizes, int n_in,
                              void* d_out, int out_size)
{
    const float* x    = (const float*)d_in[0];
    const float* Wih0 = (const float*)d_in[1];
    const float* Whh0 = (const float*)d_in[2];
    const float* bih0 = (const float*)d_in[3];
    const float* bhh0 = (const float*)d_in[4];
    const float* Wih1 = (const float*)d_in[5];
    const float* Whh1 = (const float*)d_in[6];
    const float* bih1 = (const float*)d_in[7];
    const float* bhh1 = (const float*)d_in[8];
    const float* Wlin = (const float*)d_in[9];
    const float* blin = (const float*)d_in[10];
    float* out = (float*)d_out;

    const int B = in_sizes[0] / T;              // 65536
    const int smem = SMEM_FLOATS * (int)sizeof(float);

    cudaFuncSetAttribute(k_layer0, cudaFuncAttributeMaxDynamicSharedMemorySize, smem);
    cudaFuncSetAttribute(k_gi1,    cudaFuncAttributeMaxDynamicSharedMemorySize, smem);
    cudaFuncSetAttribute(k_layer1, cudaFuncAttributeMaxDynamicSharedMemorySize, smem);

    k_init<<<(B * T + 511) / 512, 512>>>(x, B);

    const int nblk = B / BT;                    // 1024 CTAs, ~6.92 waves
    for (int i = 0; i < NB; ++i) {
        k_layer0<<<nblk, NTH, smem>>>(Whh0, Wih0, bih0, bhh0, i, B);
        k_gi1  <<<nblk, NTH, smem>>>(Wih1, bih1, B);
        k_layer1<<<nblk, NTH, smem>>>(Whh1, bhh1, Wlin, blin, out, i, B);
    }
}